// round 4
// baseline (speedup 1.0000x reference)
#include <cuda_runtime.h>
#include <math.h>

// TransformationRotationLoss — single fused streaming reduction.
// loss[j] = mean_over_masked_rows( ALPHA*u_ta[j]^2 + BETTA*u_tb[j]^2 )
//
// Raw-input algebra (a = vec_1 row, b = vec_2 row):
//   SA=Σa, SB=Σb, r1=a·a, r2=b·b, d=a·b, inv12 = rsqrt(r1*r2)
//   u_ta = (SA*b - SB*a) * inv12                       (Gram-Schmidt cancels!)
//   with g=1/r1, e=d*g, f=SB-SA*e, D=r2-d*e (=r2 sin^2), w=c-1, c=d*inv12:
//   u_tb = w*( a*(SA*g - e*f/D) + b*(f/D) )
// Only 2 MUFU per row (rsqrt.approx + rcp.approx), zero branches.

#define ALPHA 0.7f
#define BETTA 0.3f

static constexpr int THREADS    = 256;
static constexpr int MAX_BLOCKS = 4096;

__device__ float4 g_partials[MAX_BLOCKS];
__device__ unsigned int g_ticket = 0;

__device__ __forceinline__ float rcp_fast(float x) {
    float r;
    asm("rcp.approx.f32 %0, %1;" : "=f"(r) : "f"(x));
    return r;
}
__device__ __forceinline__ float rsqrt_fast(float x) {
    float r;
    asm("rsqrt.approx.f32 %0, %1;" : "=f"(r) : "f"(x));
    return r;
}

__device__ __forceinline__ void process_row(
    float ax, float ay, float az,
    float bx, float by, float bz,
    float& sx, float& sy, float& sz, float& cnt)
{
    float r1 = fmaf(ax, ax, fmaf(ay, ay, az * az));
    float r2 = fmaf(bx, bx, fmaf(by, by, bz * bz));
    float d  = fmaf(ax, bx, fmaf(ay, by, az * bz));
    float SA = ax + ay + az;
    float SB = bx + by + bz;

    float m = (r1 > 1e-16f) ? 1.0f : 0.0f;   // mask: ||v1|| > 1e-8

    // guarded denominators (keep everything finite; m zeroes bad rows)
    float r1g = fmaxf(r1, 1e-30f);
    float inv12 = rsqrt_fast(fmaxf(r1g * r2, 1e-37f));

    float c = d * inv12;
    c = fminf(1.0f, fmaxf(-1.0f, c));
    float w = c - 1.0f;

    float g = inv12 * inv12 * r2;            // 1/r1
    float e = d * g;                         // d/r1
    float f = fmaf(-SA, e, SB);              // SB - SA*e
    float D = fmaf(-d, e, r2);               // r2*sin^2 >= 0
    float fi = f * rcp_fast(fmaxf(D, 1e-30f));

    // u_tb = a*cA + b*cB
    float cA = w * fmaf(-e, fi, SA * g);
    float cB = w * fi;
    // u_ta = a*cAt + b*cBt
    float cAt = -SB * inv12;
    float cBt =  SA * inv12;

    float tax = fmaf(ax, cAt, bx * cBt);
    float tbx = fmaf(ax, cA,  bx * cB);
    float tay = fmaf(ay, cAt, by * cBt);
    float tby = fmaf(ay, cA,  by * cB);
    float taz = fmaf(az, cAt, bz * cBt);
    float tbz = fmaf(az, cA,  bz * cB);

    sx = fmaf(m, fmaf(ALPHA, tax * tax, BETTA * tbx * tbx), sx);
    sy = fmaf(m, fmaf(ALPHA, tay * tay, BETTA * tby * tby), sy);
    sz = fmaf(m, fmaf(ALPHA, taz * taz, BETTA * tbz * tbz), sz);
    cnt += m;
}

// Block-reduce (sx,sy,sz,cnt) into shared `result`; valid after return.
__device__ __forceinline__ void block_reduce(
    float sx, float sy, float sz, float cnt, float4* result)
{
    #pragma unroll
    for (int o = 16; o > 0; o >>= 1) {
        sx  += __shfl_down_sync(0xffffffffu, sx,  o);
        sy  += __shfl_down_sync(0xffffffffu, sy,  o);
        sz  += __shfl_down_sync(0xffffffffu, sz,  o);
        cnt += __shfl_down_sync(0xffffffffu, cnt, o);
    }
    __shared__ float4 smem[THREADS / 32];
    int lane = threadIdx.x & 31;
    int warp = threadIdx.x >> 5;
    if (lane == 0) smem[warp] = make_float4(sx, sy, sz, cnt);
    __syncthreads();
    if (warp == 0) {
        float4 v = (lane < (blockDim.x >> 5)) ? smem[lane]
                                              : make_float4(0.f, 0.f, 0.f, 0.f);
        sx = v.x; sy = v.y; sz = v.z; cnt = v.w;
        #pragma unroll
        for (int o = 16; o > 0; o >>= 1) {
            sx  += __shfl_down_sync(0xffffffffu, sx,  o);
            sy  += __shfl_down_sync(0xffffffffu, sy,  o);
            sz  += __shfl_down_sync(0xffffffffu, sz,  o);
            cnt += __shfl_down_sync(0xffffffffu, cnt, o);
        }
        if (lane == 0) *result = make_float4(sx, sy, sz, cnt);
    }
    __syncthreads();
}

__device__ __forceinline__ float fix_num(float x) {
    if (isnan(x)) return 0.0f;
    if (isinf(x)) return x > 0.0f ? 0.1f : -0.1f;
    return x;
}

__global__ __launch_bounds__(THREADS, 6)
void trl_fused_kernel(const float* __restrict__ v1,
                      const float* __restrict__ v2,
                      float* __restrict__ out,
                      int rows)
{
    float sx = 0.f, sy = 0.f, sz = 0.f, cnt = 0.f;

    const int tid   = blockIdx.x * blockDim.x + threadIdx.x;
    const int total = gridDim.x * blockDim.x;
    const int rows4 = rows >> 2;   // groups of 4 rows = 3 float4 per input

    const float4* __restrict__ a4 = reinterpret_cast<const float4*>(v1);
    const float4* __restrict__ b4 = reinterpret_cast<const float4*>(v2);

    if (tid < rows4) {
        float4 a0 = a4[3 * tid + 0];
        float4 a1 = a4[3 * tid + 1];
        float4 a2 = a4[3 * tid + 2];
        float4 b0 = b4[3 * tid + 0];
        float4 b1 = b4[3 * tid + 1];
        float4 b2 = b4[3 * tid + 2];

        process_row(a0.x, a0.y, a0.z, b0.x, b0.y, b0.z, sx, sy, sz, cnt);
        process_row(a0.w, a1.x, a1.y, b0.w, b1.x, b1.y, sx, sy, sz, cnt);
        process_row(a1.z, a1.w, a2.x, b1.z, b1.w, b2.x, sx, sy, sz, cnt);
        process_row(a2.y, a2.z, a2.w, b2.y, b2.z, b2.w, sx, sy, sz, cnt);
    }
    // Tail rows (rows % 4), scalar — empty when rows % 4 == 0.
    for (int r = (rows4 << 2) + tid; r < rows; r += total) {
        process_row(v1[3 * r], v1[3 * r + 1], v1[3 * r + 2],
                    v2[3 * r], v2[3 * r + 1], v2[3 * r + 2],
                    sx, sy, sz, cnt);
    }

    __shared__ float4 result;
    block_reduce(sx, sy, sz, cnt, &result);

    // Publish partial; last block to arrive finalizes.
    __shared__ bool is_last;
    if (threadIdx.x == 0) {
        g_partials[blockIdx.x] = result;
        __threadfence();
        unsigned int t = atomicAdd(&g_ticket, 1u);
        is_last = (t == gridDim.x - 1);
    }
    __syncthreads();

    if (is_last) {
        float fx = 0.f, fy = 0.f, fz = 0.f, fc = 0.f;
        for (int i = threadIdx.x; i < (int)gridDim.x; i += blockDim.x) {
            float4 p;
            const float4* src = &g_partials[i];
            asm volatile("ld.global.cg.v4.f32 {%0,%1,%2,%3}, [%4];"
                         : "=f"(p.x), "=f"(p.y), "=f"(p.z), "=f"(p.w)
                         : "l"(src));
            fx += p.x; fy += p.y; fz += p.z; fc += p.w;
        }
        __shared__ float4 final_r;
        block_reduce(fx, fy, fz, fc, &final_r);
        if (threadIdx.x == 0) {
            float inv = 1.0f / fmaxf(final_r.w, 1.0f);
            out[0] = fix_num(final_r.x * inv);
            out[1] = fix_num(final_r.y * inv);
            out[2] = fix_num(final_r.z * inv);
            g_ticket = 0;   // reset for graph replay
        }
    }
}

extern "C" void kernel_launch(void* const* d_in, const int* in_sizes, int n_in,
                              void* d_out, int out_size)
{
    const float* v1 = (const float*)d_in[0];
    const float* v2 = (const float*)d_in[1];
    float* out = (float*)d_out;

    int rows  = in_sizes[0] / 3;
    int rows4 = rows >> 2;
    int blocks = (rows4 + THREADS - 1) / THREADS;   // one group per thread
    if (blocks < 1) blocks = 1;
    if (blocks > MAX_BLOCKS) blocks = MAX_BLOCKS;

    trl_fused_kernel<<<blocks, THREADS>>>(v1, v2, out, rows);
}

// round 5
// speedup vs baseline: 1.0019x; 1.0019x over previous
#include <cuda_runtime.h>
#include <math.h>

// TransformationRotationLoss — fused streaming reduction, smem-transposed loads.
// loss[j] = mean_over_masked_rows( ALPHA*u_ta[j]^2 + BETTA*u_tb[j]^2 )
// Raw-input algebra (a=vec_1 row, b=vec_2 row):
//   u_ta = (SA*b - SB*a) * rsqrt(r1*r2)
//   u_tb = (c-1)*( a*(SA/r1 - e*f/D) + b*(f/D) ),  e=d/r1, f=SB-SA*e, D=r2-d*e

#define ALPHA 0.7f
#define BETTA 0.3f

static constexpr int THREADS    = 256;
static constexpr int ROWS_PER_BLOCK = THREADS * 4;   // 1024 rows per tile
static constexpr int F4_PER_TILE    = THREADS * 3;   // 768 float4 per input
static constexpr int MAX_BLOCKS = 4096;

__device__ float4 g_partials[MAX_BLOCKS];
__device__ unsigned int g_ticket = 0;

__device__ __forceinline__ float rcp_fast(float x) {
    float r; asm("rcp.approx.f32 %0, %1;" : "=f"(r) : "f"(x)); return r;
}
__device__ __forceinline__ float rsqrt_fast(float x) {
    float r; asm("rsqrt.approx.f32 %0, %1;" : "=f"(r) : "f"(x)); return r;
}

__device__ __forceinline__ void process_row(
    float ax, float ay, float az,
    float bx, float by, float bz,
    float& sx, float& sy, float& sz, float& cnt)
{
    float r1 = fmaf(ax, ax, fmaf(ay, ay, az * az));
    float r2 = fmaf(bx, bx, fmaf(by, by, bz * bz));
    float d  = fmaf(ax, bx, fmaf(ay, by, az * bz));
    float SA = ax + ay + az;
    float SB = bx + by + bz;

    float m = (r1 > 1e-16f) ? 1.0f : 0.0f;   // mask: ||v1|| > 1e-8

    float r1g   = fmaxf(r1, 1e-30f);
    float inv12 = rsqrt_fast(fmaxf(r1g * r2, 1e-37f));

    float c = d * inv12;
    c = fminf(1.0f, fmaxf(-1.0f, c));
    float w = c - 1.0f;

    float g = inv12 * inv12 * r2;            // 1/r1
    float e = d * g;
    float f = fmaf(-SA, e, SB);
    float D = fmaf(-d, e, r2);               // r2*sin^2 >= 0
    float fi = f * rcp_fast(fmaxf(D, 1e-30f));

    float cA  = w * fmaf(-e, fi, SA * g);
    float cB  = w * fi;
    float cAt = -SB * inv12;
    float cBt =  SA * inv12;

    float tax = fmaf(ax, cAt, bx * cBt);
    float tbx = fmaf(ax, cA,  bx * cB);
    float tay = fmaf(ay, cAt, by * cBt);
    float tby = fmaf(ay, cA,  by * cB);
    float taz = fmaf(az, cAt, bz * cBt);
    float tbz = fmaf(az, cA,  bz * cB);

    sx = fmaf(m, fmaf(ALPHA, tax * tax, BETTA * tbx * tbx), sx);
    sy = fmaf(m, fmaf(ALPHA, tay * tay, BETTA * tby * tby), sy);
    sz = fmaf(m, fmaf(ALPHA, taz * taz, BETTA * tbz * tbz), sz);
    cnt += m;
}

__device__ __forceinline__ void block_reduce(
    float sx, float sy, float sz, float cnt, float4* result)
{
    #pragma unroll
    for (int o = 16; o > 0; o >>= 1) {
        sx  += __shfl_down_sync(0xffffffffu, sx,  o);
        sy  += __shfl_down_sync(0xffffffffu, sy,  o);
        sz  += __shfl_down_sync(0xffffffffu, sz,  o);
        cnt += __shfl_down_sync(0xffffffffu, cnt, o);
    }
    __shared__ float4 rsm[THREADS / 32];
    int lane = threadIdx.x & 31;
    int warp = threadIdx.x >> 5;
    if (lane == 0) rsm[warp] = make_float4(sx, sy, sz, cnt);
    __syncthreads();
    if (warp == 0) {
        float4 v = (lane < (blockDim.x >> 5)) ? rsm[lane]
                                              : make_float4(0.f, 0.f, 0.f, 0.f);
        sx = v.x; sy = v.y; sz = v.z; cnt = v.w;
        #pragma unroll
        for (int o = 16; o > 0; o >>= 1) {
            sx  += __shfl_down_sync(0xffffffffu, sx,  o);
            sy  += __shfl_down_sync(0xffffffffu, sy,  o);
            sz  += __shfl_down_sync(0xffffffffu, sz,  o);
            cnt += __shfl_down_sync(0xffffffffu, cnt, o);
        }
        if (lane == 0) *result = make_float4(sx, sy, sz, cnt);
    }
    __syncthreads();
}

__device__ __forceinline__ float fix_num(float x) {
    if (isnan(x)) return 0.0f;
    if (isinf(x)) return x > 0.0f ? 0.1f : -0.1f;
    return x;
}

__global__ __launch_bounds__(THREADS, 6)
void trl_fused_kernel(const float* __restrict__ v1,
                      const float* __restrict__ v2,
                      float* __restrict__ out,
                      int rows)
{
    __shared__ float4 sa[F4_PER_TILE];
    __shared__ float4 sb[F4_PER_TILE];

    float sx = 0.f, sy = 0.f, sz = 0.f, cnt = 0.f;

    const int tid   = threadIdx.x;
    const int tiles = (rows + ROWS_PER_BLOCK - 1) / ROWS_PER_BLOCK;

    const float4* __restrict__ a4 = reinterpret_cast<const float4*>(v1);
    const float4* __restrict__ b4 = reinterpret_cast<const float4*>(v2);

    for (int t = blockIdx.x; t < tiles; t += gridDim.x) {
        long tile_row0 = (long)t * ROWS_PER_BLOCK;
        if (tile_row0 + ROWS_PER_BLOCK <= rows) {
            // Fast path: fully-coalesced LDG.128, transpose via smem.
            int fb = t * F4_PER_TILE;
            float4 a0 = a4[fb + tid];
            float4 a1 = a4[fb + tid + THREADS];
            float4 a2 = a4[fb + tid + 2 * THREADS];
            float4 b0 = b4[fb + tid];
            float4 b1 = b4[fb + tid + THREADS];
            float4 b2 = b4[fb + tid + 2 * THREADS];
            sa[tid]               = a0;
            sa[tid + THREADS]     = a1;
            sa[tid + 2 * THREADS] = a2;
            sb[tid]               = b0;
            sb[tid + THREADS]     = b1;
            sb[tid + 2 * THREADS] = b2;
            __syncthreads();

            float4 A0 = sa[3 * tid + 0];
            float4 A1 = sa[3 * tid + 1];
            float4 A2 = sa[3 * tid + 2];
            float4 B0 = sb[3 * tid + 0];
            float4 B1 = sb[3 * tid + 1];
            float4 B2 = sb[3 * tid + 2];

            process_row(A0.x, A0.y, A0.z, B0.x, B0.y, B0.z, sx, sy, sz, cnt);
            process_row(A0.w, A1.x, A1.y, B0.w, B1.x, B1.y, sx, sy, sz, cnt);
            process_row(A1.z, A1.w, A2.x, B1.z, B1.w, B2.x, sx, sy, sz, cnt);
            process_row(A2.y, A2.z, A2.w, B2.y, B2.z, B2.w, sx, sy, sz, cnt);
            __syncthreads();   // smem reusable next tile iteration
        } else {
            // Tail tile: scalar per-row.
            for (long r = tile_row0 + tid; r < rows; r += THREADS) {
                process_row(v1[3 * r], v1[3 * r + 1], v1[3 * r + 2],
                            v2[3 * r], v2[3 * r + 1], v2[3 * r + 2],
                            sx, sy, sz, cnt);
            }
        }
    }

    __shared__ float4 result;
    block_reduce(sx, sy, sz, cnt, &result);

    // Publish partial; last block to arrive finalizes.
    __shared__ bool is_last;
    if (threadIdx.x == 0) {
        g_partials[blockIdx.x] = result;
        __threadfence();
        unsigned int tk = atomicAdd(&g_ticket, 1u);
        is_last = (tk == gridDim.x - 1);
    }
    __syncthreads();

    if (is_last) {
        float fx = 0.f, fy = 0.f, fz = 0.f, fc = 0.f;
        for (int i = threadIdx.x; i < (int)gridDim.x; i += blockDim.x) {
            float4 p;
            const float4* src = &g_partials[i];
            asm volatile("ld.global.cg.v4.f32 {%0,%1,%2,%3}, [%4];"
                         : "=f"(p.x), "=f"(p.y), "=f"(p.z), "=f"(p.w)
                         : "l"(src));
            fx += p.x; fy += p.y; fz += p.z; fc += p.w;
        }
        __shared__ float4 final_r;
        block_reduce(fx, fy, fz, fc, &final_r);
        if (threadIdx.x == 0) {
            float inv = 1.0f / fmaxf(final_r.w, 1.0f);
            out[0] = fix_num(final_r.x * inv);
            out[1] = fix_num(final_r.y * inv);
            out[2] = fix_num(final_r.z * inv);
            g_ticket = 0;   // reset for graph replay
        }
    }
}

extern "C" void kernel_launch(void* const* d_in, const int* in_sizes, int n_in,
                              void* d_out, int out_size)
{
    const float* v1 = (const float*)d_in[0];
    const float* v2 = (const float*)d_in[1];
    float* out = (float*)d_out;

    int rows  = in_sizes[0] / 3;
    int tiles = (rows + ROWS_PER_BLOCK - 1) / ROWS_PER_BLOCK;
    int blocks = tiles;
    if (blocks < 1) blocks = 1;
    if (blocks > MAX_BLOCKS) blocks = MAX_BLOCKS;

    trl_fused_kernel<<<blocks, THREADS>>>(v1, v2, out, rows);
}

// round 6
// speedup vs baseline: 1.1552x; 1.1530x over previous
#include <cuda_runtime.h>
#include <math.h>
#include <stdint.h>

// TransformationRotationLoss — persistent blocks + cp.async.bulk (TMA-path)
// 3-stage smem pipeline. loss[j] = mean_masked( A*u_ta^2 + B*u_tb^2 ).
//   u_ta = (SA*b - SB*a) * rsqrt(r1*r2)
//   u_tb = (c-1)*( a*(SA/r1 - e*f/D) + b*(f/D) ), e=d/r1, f=SB-SA*e, D=r2-d*e

#define ALPHA 0.7f
#define BETTA 0.3f

static constexpr int THREADS    = 256;
static constexpr int STAGES     = 3;
static constexpr int TILE_ROWS  = 1024;                 // rows per tile
static constexpr int TILE_F4    = TILE_ROWS * 3 / 4;    // 768 float4 per input
static constexpr int TILE_BYTES = TILE_F4 * 16;         // 12288 B per input
static constexpr int GRID_BLOCKS = 444;                 // 148 SMs * 3 CTAs
static constexpr int MAX_BLOCKS  = 1024;

__device__ float4 g_partials[MAX_BLOCKS];
__device__ unsigned int g_ticket = 0;

__device__ __forceinline__ float rcp_fast(float x) {
    float r; asm("rcp.approx.f32 %0, %1;" : "=f"(r) : "f"(x)); return r;
}
__device__ __forceinline__ float rsqrt_fast(float x) {
    float r; asm("rsqrt.approx.f32 %0, %1;" : "=f"(r) : "f"(x)); return r;
}
__device__ __forceinline__ uint32_t smem_u32(const void* p) {
    uint32_t a;
    asm("{ .reg .u64 t; cvta.to.shared.u64 t, %1; cvt.u32.u64 %0, t; }"
        : "=r"(a) : "l"(p));
    return a;
}
__device__ __forceinline__ void mbar_init(uint32_t mbar, uint32_t count) {
    asm volatile("mbarrier.init.shared.b64 [%0], %1;" :: "r"(mbar), "r"(count) : "memory");
}
__device__ __forceinline__ void mbar_expect_tx(uint32_t mbar, uint32_t bytes) {
    asm volatile("mbarrier.arrive.expect_tx.shared.b64 _, [%0], %1;"
                 :: "r"(mbar), "r"(bytes) : "memory");
}
__device__ __forceinline__ void mbar_wait(uint32_t mbar, uint32_t parity) {
    uint32_t done;
    asm volatile(
        "{\n\t.reg .pred p;\n\t"
        "mbarrier.try_wait.parity.acquire.cta.shared::cta.b64 p, [%1], %2;\n\t"
        "selp.b32 %0, 1, 0, p;\n\t}"
        : "=r"(done) : "r"(mbar), "r"(parity) : "memory");
    if (!done) {
        asm volatile(
            "{\n\t.reg .pred P1;\n\t"
            "W_%=:\n\t"
            "mbarrier.try_wait.parity.acquire.cta.shared::cta.b64 P1, [%0], %1, 0x989680;\n\t"
            "@P1 bra.uni D_%=;\n\t"
            "bra.uni W_%=;\n\t"
            "D_%=:\n\t}"
            :: "r"(mbar), "r"(parity) : "memory");
    }
}
__device__ __forceinline__ void bulk_g2s(uint32_t dst_smem, const void* src_gmem,
                                         uint32_t bytes, uint32_t mbar) {
    asm volatile(
        "cp.async.bulk.shared::cluster.global.mbarrier::complete_tx::bytes "
        "[%0], [%1], %2, [%3];"
        :: "r"(dst_smem), "l"(src_gmem), "r"(bytes), "r"(mbar) : "memory");
}

__device__ __forceinline__ void process_row(
    float ax, float ay, float az,
    float bx, float by, float bz,
    float& sx, float& sy, float& sz, float& cnt)
{
    float r1 = fmaf(ax, ax, fmaf(ay, ay, az * az));
    float r2 = fmaf(bx, bx, fmaf(by, by, bz * bz));
    float d  = fmaf(ax, bx, fmaf(ay, by, az * bz));
    float SA = ax + ay + az;
    float SB = bx + by + bz;

    float m = (r1 > 1e-16f) ? 1.0f : 0.0f;   // mask: ||v1|| > 1e-8

    float r1g   = fmaxf(r1, 1e-30f);
    float inv12 = rsqrt_fast(fmaxf(r1g * r2, 1e-37f));

    float c = d * inv12;
    c = fminf(1.0f, fmaxf(-1.0f, c));
    float w = c - 1.0f;

    float g = inv12 * inv12 * r2;            // 1/r1
    float e = d * g;
    float f = fmaf(-SA, e, SB);
    float D = fmaf(-d, e, r2);               // r2*sin^2 >= 0
    float fi = f * rcp_fast(fmaxf(D, 1e-30f));

    float cA  = w * fmaf(-e, fi, SA * g);
    float cB  = w * fi;
    float cAt = -SB * inv12;
    float cBt =  SA * inv12;

    float tax = fmaf(ax, cAt, bx * cBt);
    float tbx = fmaf(ax, cA,  bx * cB);
    float tay = fmaf(ay, cAt, by * cBt);
    float tby = fmaf(ay, cA,  by * cB);
    float taz = fmaf(az, cAt, bz * cBt);
    float tbz = fmaf(az, cA,  bz * cB);

    sx = fmaf(m, fmaf(ALPHA, tax * tax, BETTA * tbx * tbx), sx);
    sy = fmaf(m, fmaf(ALPHA, tay * tay, BETTA * tby * tby), sy);
    sz = fmaf(m, fmaf(ALPHA, taz * taz, BETTA * tbz * tbz), sz);
    cnt += m;
}

__device__ __forceinline__ void block_reduce(
    float sx, float sy, float sz, float cnt, float4* result)
{
    #pragma unroll
    for (int o = 16; o > 0; o >>= 1) {
        sx  += __shfl_down_sync(0xffffffffu, sx,  o);
        sy  += __shfl_down_sync(0xffffffffu, sy,  o);
        sz  += __shfl_down_sync(0xffffffffu, sz,  o);
        cnt += __shfl_down_sync(0xffffffffu, cnt, o);
    }
    __shared__ float4 rsm[THREADS / 32];
    int lane = threadIdx.x & 31;
    int warp = threadIdx.x >> 5;
    if (lane == 0) rsm[warp] = make_float4(sx, sy, sz, cnt);
    __syncthreads();
    if (warp == 0) {
        float4 v = (lane < (blockDim.x >> 5)) ? rsm[lane]
                                              : make_float4(0.f, 0.f, 0.f, 0.f);
        sx = v.x; sy = v.y; sz = v.z; cnt = v.w;
        #pragma unroll
        for (int o = 16; o > 0; o >>= 1) {
            sx  += __shfl_down_sync(0xffffffffu, sx,  o);
            sy  += __shfl_down_sync(0xffffffffu, sy,  o);
            sz  += __shfl_down_sync(0xffffffffu, sz,  o);
            cnt += __shfl_down_sync(0xffffffffu, cnt, o);
        }
        if (lane == 0) *result = make_float4(sx, sy, sz, cnt);
    }
    __syncthreads();
}

__device__ __forceinline__ float fix_num(float x) {
    if (isnan(x)) return 0.0f;
    if (isinf(x)) return x > 0.0f ? 0.1f : -0.1f;
    return x;
}

extern __shared__ unsigned char dynsmem[];

__global__ __launch_bounds__(THREADS)
void trl_tma_kernel(const float* __restrict__ v1,
                    const float* __restrict__ v2,
                    float* __restrict__ out,
                    int rows)
{
    float4* sA = reinterpret_cast<float4*>(dynsmem);                 // STAGES*768
    float4* sB = sA + STAGES * TILE_F4;
    uint64_t* mbar = reinterpret_cast<uint64_t*>(sB + STAGES * TILE_F4);

    const int tid = threadIdx.x;
    uint32_t mbar_addr[STAGES];
    #pragma unroll
    for (int s = 0; s < STAGES; s++) mbar_addr[s] = smem_u32(&mbar[s]);

    if (tid == 0) {
        #pragma unroll
        for (int s = 0; s < STAGES; s++) mbar_init(mbar_addr[s], 1);
    }
    __syncthreads();

    float sx = 0.f, sy = 0.f, sz = 0.f, cnt = 0.f;

    const int tiles = rows / TILE_ROWS;        // full tiles via bulk path
    const int G = gridDim.x, b = blockIdx.x;
    const int n_my = (tiles > b) ? ((tiles - 1 - b) / G + 1) : 0;

    // Prologue: issue up to STAGES tile loads.
    if (tid == 0) {
        int prol = n_my < STAGES ? n_my : STAGES;
        for (int p = 0; p < prol; p++) {
            long t = (long)b + (long)p * G;
            mbar_expect_tx(mbar_addr[p], 2 * TILE_BYTES);
            bulk_g2s(smem_u32(sA + p * TILE_F4), v1 + t * (TILE_ROWS * 3),
                     TILE_BYTES, mbar_addr[p]);
            bulk_g2s(smem_u32(sB + p * TILE_F4), v2 + t * (TILE_ROWS * 3),
                     TILE_BYTES, mbar_addr[p]);
        }
    }

    for (int i = 0; i < n_my; i++) {
        int s = i % STAGES;
        uint32_t parity = (uint32_t)((i / STAGES) & 1);
        mbar_wait(mbar_addr[s], parity);

        const float4* A = sA + s * TILE_F4;
        const float4* B = sB + s * TILE_F4;
        float4 A0 = A[3 * tid + 0];
        float4 A1 = A[3 * tid + 1];
        float4 A2 = A[3 * tid + 2];
        float4 B0 = B[3 * tid + 0];
        float4 B1 = B[3 * tid + 1];
        float4 B2 = B[3 * tid + 2];

        process_row(A0.x, A0.y, A0.z, B0.x, B0.y, B0.z, sx, sy, sz, cnt);
        process_row(A0.w, A1.x, A1.y, B0.w, B1.x, B1.y, sx, sy, sz, cnt);
        process_row(A1.z, A1.w, A2.x, B1.z, B1.w, B2.x, sx, sy, sz, cnt);
        process_row(A2.y, A2.z, A2.w, B2.y, B2.z, B2.w, sx, sy, sz, cnt);

        __syncthreads();   // all threads done reading slot s
        if (tid == 0 && i + STAGES < n_my) {
            long t = (long)b + (long)(i + STAGES) * G;
            mbar_expect_tx(mbar_addr[s], 2 * TILE_BYTES);
            bulk_g2s(smem_u32(sA + s * TILE_F4), v1 + t * (TILE_ROWS * 3),
                     TILE_BYTES, mbar_addr[s]);
            bulk_g2s(smem_u32(sB + s * TILE_F4), v2 + t * (TILE_ROWS * 3),
                     TILE_BYTES, mbar_addr[s]);
        }
    }

    // Tail rows (rows % TILE_ROWS), scalar across all blocks.
    for (long r = (long)tiles * TILE_ROWS + b * THREADS + tid; r < rows;
         r += (long)G * THREADS) {
        process_row(v1[3 * r], v1[3 * r + 1], v1[3 * r + 2],
                    v2[3 * r], v2[3 * r + 1], v2[3 * r + 2],
                    sx, sy, sz, cnt);
    }

    __shared__ float4 result;
    block_reduce(sx, sy, sz, cnt, &result);

    __shared__ bool is_last;
    if (tid == 0) {
        g_partials[blockIdx.x] = result;
        __threadfence();
        unsigned int tk = atomicAdd(&g_ticket, 1u);
        is_last = (tk == gridDim.x - 1);
    }
    __syncthreads();

    if (is_last) {
        float fx = 0.f, fy = 0.f, fz = 0.f, fc = 0.f;
        for (int i = tid; i < (int)gridDim.x; i += blockDim.x) {
            float4 p;
            const float4* src = &g_partials[i];
            asm volatile("ld.global.cg.v4.f32 {%0,%1,%2,%3}, [%4];"
                         : "=f"(p.x), "=f"(p.y), "=f"(p.z), "=f"(p.w)
                         : "l"(src));
            fx += p.x; fy += p.y; fz += p.z; fc += p.w;
        }
        __shared__ float4 final_r;
        block_reduce(fx, fy, fz, fc, &final_r);
        if (tid == 0) {
            float inv = 1.0f / fmaxf(final_r.w, 1.0f);
            out[0] = fix_num(final_r.x * inv);
            out[1] = fix_num(final_r.y * inv);
            out[2] = fix_num(final_r.z * inv);
            g_ticket = 0;   // reset for graph replay
        }
    }
}

extern "C" void kernel_launch(void* const* d_in, const int* in_sizes, int n_in,
                              void* d_out, int out_size)
{
    const float* v1 = (const float*)d_in[0];
    const float* v2 = (const float*)d_in[1];
    float* out = (float*)d_out;

    int rows = in_sizes[0] / 3;
    int blocks = GRID_BLOCKS;
    if (blocks > MAX_BLOCKS) blocks = MAX_BLOCKS;

    size_t shmem = (size_t)STAGES * 2 * TILE_F4 * sizeof(float4)
                 + STAGES * sizeof(uint64_t) + 16;
    cudaFuncSetAttribute(trl_tma_kernel,
                         cudaFuncAttributeMaxDynamicSharedMemorySize,
                         (int)shmem);

    trl_tma_kernel<<<blocks, THREADS, shmem>>>(v1, v2, out, rows);
}